// round 11
// baseline (speedup 1.0000x reference)
#include <cuda_runtime.h>
#include <cuda_fp16.h>
#include <cstdint>

#define MAXN 100000
#define CAP 128            // per-node CSR bucket capacity, multiple of 16
#define ZOFF (MAXN << 7)   // byte offset of the permanently-zero h' row

// Scratch (__device__ globals; allocation-free rule)
// g_A has one extra row (index MAXN): BSS-zeroed, never written -> stays zero.
__device__ __align__(16) __half g_A[(MAXN + 1) * 64];
__device__ __align__(16) float  g_B[MAXN * 64];   // agg out (fp32 or fp16-aliased)
__device__ int g_cnt[MAXN];
__device__ __align__(16) int g_csr[MAXN * CAP];  // src row BYTE offsets (s<<7)

// ---------------------------------------------------------------------------
// prep
// ---------------------------------------------------------------------------
__global__ void zero_k(int N) {
    int i = blockIdx.x * blockDim.x + threadIdx.x;
    if (i < N) g_cnt[i] = 0;
}

__global__ void fill_k(const int* __restrict__ ei, int E, int N) {
    int e = blockIdx.x * blockDim.x + threadIdx.x;
    if (e >= E) return;
    int s = __ldg(ei + e);
    int d = __ldg(ei + (size_t)E + e);
    if ((unsigned)s >= (unsigned)N) s = 0;
    if ((unsigned)d >= (unsigned)N) d = 0;
    int pos = atomicAdd(&g_cnt[d], 1);
    if (pos < CAP) g_csr[(size_t)d * CAP + pos] = s << 7;
}

__global__ void pad_k(int N) {
    int i = blockIdx.x * blockDim.x + threadIdx.x;
    if (i >= N) return;
    int c = g_cnt[i];
    if (c > CAP) c = CAP;
    int end = (c + 15) & ~15;
    int* row = g_csr + (size_t)i * CAP;
    for (int j = c; j < end; j++) row[j] = ZOFF;
}

// ---------------------------------------------------------------------------
// tf32 helpers
// ---------------------------------------------------------------------------
__device__ __forceinline__ unsigned f2tf32(float f) {
    unsigned r;
    asm("cvt.rna.tf32.f32 %0, %1;" : "=r"(r) : "f"(f));
    return r;
}

__device__ __forceinline__ void mma_tf32(float* c, unsigned a0, unsigned a1,
                                         unsigned a2, unsigned a3,
                                         unsigned b0, unsigned b1) {
    asm volatile(
        "mma.sync.aligned.m16n8k8.row.col.f32.tf32.tf32.f32 "
        "{%0,%1,%2,%3}, {%4,%5,%6,%7}, {%8,%9}, {%0,%1,%2,%3};"
        : "+f"(c[0]), "+f"(c[1]), "+f"(c[2]), "+f"(c[3])
        : "r"(a0), "r"(a1), "r"(a2), "r"(a3), "r"(b0), "r"(b1));
}

// ---------------------------------------------------------------------------
// Layer GEMM (tensor): out[N,64] = (in[N,64] @ W[64,64]) * dinv[row] -> fp16.
// 256 thr / 8 warps, 128-row tile. XOR-swizzled smem (exactly 48KB):
//   xs col' = c ^ ((r&7)<<2)   Wsh col' = c ^ ((k&3)<<3)
// Input IT = float (layer 1, raw x) or __half (layer 2, pre-activated by agg).
// ---------------------------------------------------------------------------
template <typename IT>
__global__ void __launch_bounds__(256) gemm_mma_k(
        const IT* __restrict__ in, const float* __restrict__ W,
        __half* __restrict__ out, int N) {
    __shared__ unsigned xs[128 * 64];
    __shared__ unsigned Wsh[64 * 64];

    const int t = threadIdx.x;
    const int row0 = blockIdx.x * 128;

    #pragma unroll
    for (int i = t; i < 64 * 64; i += 256) {
        int k = i >> 6, c = i & 63;
        Wsh[k * 64 + (c ^ ((k & 3) << 3))] = f2tf32(W[i]);
    }

    #pragma unroll
    for (int i = t; i < 128 * 64; i += 256) {
        int r = i >> 6, c = i & 63;
        int gr = row0 + r;
        float v = 0.0f;
        if (gr < N) {
            if constexpr (sizeof(IT) == 2)
                v = __half2float(((const __half*)in)[(size_t)gr * 64 + c]);
            else
                v = ((const float*)in)[(size_t)gr * 64 + c];
        }
        xs[r * 64 + (c ^ ((r & 7) << 2))] = f2tf32(v);
    }
    __syncthreads();

    const int lane = t & 31;
    const int gid = lane >> 2;      // 0..7
    const int tig = lane & 3;       // 0..3
    const int wr  = (t >> 5) * 16;  // warp row base in tile (8 warps x 16)

    float acc[8][4];
    #pragma unroll
    for (int ng = 0; ng < 8; ng++)
        #pragma unroll
        for (int j = 0; j < 4; j++) acc[ng][j] = 0.0f;

    const int ra = wr + gid, rb = wr + gid + 8;
    const int sa = (ra & 7) << 2, sb = (rb & 7) << 2;

    #pragma unroll
    for (int k0 = 0; k0 < 64; k0 += 8) {
        unsigned a0 = xs[ra * 64 + ((k0 + tig) ^ sa)];
        unsigned a1 = xs[rb * 64 + ((k0 + tig) ^ sb)];
        unsigned a2 = xs[ra * 64 + ((k0 + tig + 4) ^ sa)];
        unsigned a3 = xs[rb * 64 + ((k0 + tig + 4) ^ sb)];
        const int swz = tig << 3;   // (k&3)<<3 for k=k0+tig and k0+tig+4
        #pragma unroll
        for (int ng = 0; ng < 8; ng++) {
            unsigned b0 = Wsh[(k0 + tig) * 64 + ((ng * 8 + gid) ^ swz)];
            unsigned b1 = Wsh[(k0 + tig + 4) * 64 + ((ng * 8 + gid) ^ swz)];
            mma_tf32(acc[ng], a0, a1, a2, a3, b0, b1);
        }
    }

    int r1 = row0 + wr + gid;
    int r2 = r1 + 8;
    float sc1 = (r1 < N) ? rsqrtf((float)g_cnt[r1] + 1.0f) : 0.0f;
    float sc2 = (r2 < N) ? rsqrtf((float)g_cnt[r2] + 1.0f) : 0.0f;

    #pragma unroll
    for (int ng = 0; ng < 8; ng++) {
        int col = ng * 8 + 2 * tig;
        if (r1 < N)
            *reinterpret_cast<__half2*>(out + (size_t)r1 * 64 + col) =
                __floats2half2_rn(acc[ng][0] * sc1, acc[ng][1] * sc1);
        if (r2 < N)
            *reinterpret_cast<__half2*>(out + (size_t)r2 * 64 + col) =
                __floats2half2_rn(acc[ng][2] * sc2, acc[ng][3] * sc2);
    }
}

// ---------------------------------------------------------------------------
// Head GEMM (fp32 FFMA): out[N,32] = relu(in + preb) @ Wf + postb
// ---------------------------------------------------------------------------
__global__ void __launch_bounds__(256) gemm_head_k(
        const float* __restrict__ in, const float* __restrict__ W,
        const float* __restrict__ preb, const float* __restrict__ postb,
        float* __restrict__ out, int N) {
    constexpr int NOUT = 32, CPT = 2;
    __shared__ float xs[64][65];
    __shared__ __align__(16) float Ws[64 * NOUT];

    const int t = threadIdx.x;
    const int row0 = blockIdx.x * 64;

    #pragma unroll
    for (int i = t; i < 64 * NOUT; i += 256) Ws[i] = W[i];

    #pragma unroll
    for (int i = 0; i < 16; i++) {
        int lin = t + i * 256;
        int r = lin >> 6, c = lin & 63;
        int gr = row0 + r;
        float v = (gr < N) ? in[(size_t)gr * 64 + c] : 0.0f;
        v = fmaxf(v + preb[c], 0.0f);
        xs[r][c] = v;
    }
    __syncthreads();

    const int r0 = (t >> 4) * 4;
    const int c0 = (t & 15) * CPT;

    float acc[4][CPT];
    #pragma unroll
    for (int i = 0; i < 4; i++)
        #pragma unroll
        for (int j = 0; j < CPT; j++) acc[i][j] = 0.0f;

    #pragma unroll
    for (int k = 0; k < 64; k++) {
        float wv[CPT];
        #pragma unroll
        for (int j = 0; j < CPT; j++) wv[j] = Ws[k * NOUT + c0 + j];
        #pragma unroll
        for (int i = 0; i < 4; i++) {
            float a = xs[r0 + i][k];
            #pragma unroll
            for (int j = 0; j < CPT; j++)
                acc[i][j] = fmaf(a, wv[j], acc[i][j]);
        }
    }

    #pragma unroll
    for (int i = 0; i < 4; i++) {
        int gr = row0 + r0 + i;
        if (gr < N) {
            #pragma unroll
            for (int j = 0; j < CPT; j++)
                out[(size_t)gr * NOUT + c0 + j] = acc[i][j] + postb[c0 + j];
        }
    }
}

// ---------------------------------------------------------------------------
// Aggregation: warp per node, quarter-warp gathers, fp16 4-edge tree.
// ACT=true: write relu(res + bias) as fp16 (feeds tf32 gemm; fp16 mantissa ==
// tf32 mantissa so no extra loss). ACT=false: write fp32 (feeds fp32 head).
// ---------------------------------------------------------------------------
__device__ __forceinline__ uint4 hadd2_u4(uint4 a, uint4 b) {
    uint4 r;
    *reinterpret_cast<__half2*>(&r.x) = __hadd2(*reinterpret_cast<__half2*>(&a.x),
                                                *reinterpret_cast<__half2*>(&b.x));
    *reinterpret_cast<__half2*>(&r.y) = __hadd2(*reinterpret_cast<__half2*>(&a.y),
                                                *reinterpret_cast<__half2*>(&b.y));
    *reinterpret_cast<__half2*>(&r.z) = __hadd2(*reinterpret_cast<__half2*>(&a.z),
                                                *reinterpret_cast<__half2*>(&b.z));
    *reinterpret_cast<__half2*>(&r.w) = __hadd2(*reinterpret_cast<__half2*>(&a.w),
                                                *reinterpret_cast<__half2*>(&b.w));
    return r;
}

__device__ __forceinline__ void addf32_u4(float* acc, uint4 v) {
    float2 f;
    f = __half22float2(*reinterpret_cast<__half2*>(&v.x)); acc[0] += f.x; acc[1] += f.y;
    f = __half22float2(*reinterpret_cast<__half2*>(&v.y)); acc[2] += f.x; acc[3] += f.y;
    f = __half22float2(*reinterpret_cast<__half2*>(&v.z)); acc[4] += f.x; acc[5] += f.y;
    f = __half22float2(*reinterpret_cast<__half2*>(&v.w)); acc[6] += f.x; acc[7] += f.y;
}

template <bool ACT>
__global__ void __launch_bounds__(256) agg_k(
        float* __restrict__ outb, const float* __restrict__ bias, int N) {
    int warp = (blockIdx.x * blockDim.x + threadIdx.x) >> 5;
    int lane = threadIdx.x & 31;
    if (warp >= N) return;
    int q = lane & 7;
    int g = lane >> 3;

    const char* __restrict__ hbase = reinterpret_cast<const char*>(g_A) + q * 16;
    const int*  __restrict__ row   = g_csr + (size_t)warp * CAP;
    int cnt = g_cnt[warp];
    if (cnt > CAP) cnt = CAP;

    float acc[8] = {0, 0, 0, 0, 0, 0, 0, 0};

    if (g == 0) {   // self-loop row
        uint4 v = *reinterpret_cast<const uint4*>(hbase + (size_t)warp * 128);
        addf32_u4(acc, v);
    }

    for (int b = 0; b < cnt; b += 16) {
        int4 idx = *reinterpret_cast<const int4*>(row + b + 4 * g);
        uint4 v0 = *reinterpret_cast<const uint4*>(hbase + idx.x);
        uint4 v1 = *reinterpret_cast<const uint4*>(hbase + idx.y);
        uint4 v2 = *reinterpret_cast<const uint4*>(hbase + idx.z);
        uint4 v3 = *reinterpret_cast<const uint4*>(hbase + idx.w);
        uint4 t = hadd2_u4(hadd2_u4(v0, v1), hadd2_u4(v2, v3));
        addf32_u4(acc, t);
    }

    #pragma unroll
    for (int i = 0; i < 8; i++) {
        acc[i] += __shfl_xor_sync(0xffffffffu, acc[i], 8);
        acc[i] += __shfl_xor_sync(0xffffffffu, acc[i], 16);
    }

    float di = rsqrtf((float)g_cnt[warp] + 1.0f);
    if (g < 2) {
        int col = q * 8 + g * 4;
        if constexpr (ACT) {
            float v0 = fmaxf(acc[g * 4 + 0] * di + bias[col + 0], 0.0f);
            float v1 = fmaxf(acc[g * 4 + 1] * di + bias[col + 1], 0.0f);
            float v2 = fmaxf(acc[g * 4 + 2] * di + bias[col + 2], 0.0f);
            float v3 = fmaxf(acc[g * 4 + 3] * di + bias[col + 3], 0.0f);
            __half2* hout = reinterpret_cast<__half2*>(outb);
            hout[((size_t)warp * 64 + col) >> 1]       = __floats2half2_rn(v0, v1);
            hout[(((size_t)warp * 64 + col) >> 1) + 1] = __floats2half2_rn(v2, v3);
        } else {
            float4 w = make_float4(acc[g * 4 + 0] * di, acc[g * 4 + 1] * di,
                                   acc[g * 4 + 2] * di, acc[g * 4 + 3] * di);
            *reinterpret_cast<float4*>(outb + (size_t)warp * 64 + col) = w;
        }
    }
}

// ---------------------------------------------------------------------------
// launch
// ---------------------------------------------------------------------------
extern "C" void kernel_launch(void* const* d_in, const int* in_sizes, int n_in,
                              void* d_out, int out_size) {
    const float* x  = (const float*)d_in[0];
    const int*   ei = (const int*)d_in[1];
    const float* W1 = (const float*)d_in[2];
    const float* b1 = (const float*)d_in[3];
    const float* W2 = (const float*)d_in[4];
    const float* b2 = (const float*)d_in[5];
    const float* Wf = (const float*)d_in[6];
    const float* bf = (const float*)d_in[7];
    float* out = (float*)d_out;

    const int N = in_sizes[0] / 64;
    const int E = in_sizes[1] / 2;

    __half* pA = nullptr;
    float*  pB = nullptr;
    cudaGetSymbolAddress((void**)&pA, g_A);
    cudaGetSymbolAddress((void**)&pB, g_B);

    const int T = 256;
    dim3 bn((N + T - 1) / T), be((E + T - 1) / T);
    dim3 bg128((N + 127) / 128), bg64((N + 63) / 64);
    dim3 bagg((N * 32 + T - 1) / T);

    zero_k<<<bn, T>>>(N);
    fill_k<<<be, T>>>(ei, E, N);
    pad_k<<<bn, T>>>(N);

    // layer 1: h' = (x @ W1) * dinv (tf32 MMA, fp16 out)
    gemm_mma_k<float><<<bg128, T>>>(x, W1, pA, N);
    // agg 1: writes relu(agg*dinv + b1) as fp16 into g_B
    agg_k<true><<<bagg, T>>>(pB, b1, N);

    // layer 2: h' = (act1 @ W2) * dinv (fp16 in, tf32 MMA, fp16 out)
    gemm_mma_k<__half><<<bg128, T>>>((const __half*)pB, W2, pA, N);
    // agg 2: plain fp32 output for the head
    agg_k<false><<<bagg, T>>>(pB, nullptr, N);

    // head: out = relu(agg2 + b2) @ Wf + bf (fp32 FFMA)
    gemm_head_k<<<bg64, T>>>(pB, Wf, b2, bf, out, N);
}

// round 12
// speedup vs baseline: 1.0806x; 1.0806x over previous
#include <cuda_runtime.h>
#include <cuda_fp16.h>
#include <cstdint>

#define MAXN 100000
#define CAP 128            // per-node CSR bucket capacity, multiple of 16
#define ZOFF (MAXN << 7)   // byte offset of the permanently-zero h' row

// Scratch (__device__ globals; allocation-free rule)
__device__ __align__(16) __half g_A[(MAXN + 1) * 64];  // h' fp16; row MAXN stays 0
__device__ __align__(16) float  g_B[MAXN * 64];        // agg out (fp32 or fp16-aliased)
__device__ int g_cnt[MAXN];
__device__ __align__(16) int g_csr[MAXN * CAP];        // src row BYTE offsets (s<<7)

// ---------------------------------------------------------------------------
// prep
// ---------------------------------------------------------------------------
__global__ void zero_k(int N) {
    int i = blockIdx.x * blockDim.x + threadIdx.x;
    if (i < N) g_cnt[i] = 0;
}

__global__ void fill_k(const int* __restrict__ ei, int E, int N) {
    int e = blockIdx.x * blockDim.x + threadIdx.x;
    if (e >= E) return;
    int s = __ldg(ei + e);
    int d = __ldg(ei + (size_t)E + e);
    if ((unsigned)s >= (unsigned)N) s = 0;
    if ((unsigned)d >= (unsigned)N) d = 0;
    int pos = atomicAdd(&g_cnt[d], 1);
    if (pos < CAP) g_csr[(size_t)d * CAP + pos] = s << 7;
}

__global__ void pad_k(int N) {
    int i = blockIdx.x * blockDim.x + threadIdx.x;
    if (i >= N) return;
    int c = g_cnt[i];
    if (c > CAP) c = CAP;
    int end = (c + 15) & ~15;
    int* row = g_csr + (size_t)i * CAP;
    for (int j = c; j < end; j++) row[j] = ZOFF;
}

// ---------------------------------------------------------------------------
// HMMA helpers
// ---------------------------------------------------------------------------
__device__ __forceinline__ void ldsm_x4(unsigned& r0, unsigned& r1,
                                        unsigned& r2, unsigned& r3, unsigned addr) {
    asm volatile("ldmatrix.sync.aligned.m8n8.x4.shared.b16 {%0,%1,%2,%3}, [%4];"
                 : "=r"(r0), "=r"(r1), "=r"(r2), "=r"(r3) : "r"(addr));
}
__device__ __forceinline__ void ldsm_x2(unsigned& r0, unsigned& r1, unsigned addr) {
    asm volatile("ldmatrix.sync.aligned.m8n8.x2.shared.b16 {%0,%1}, [%2];"
                 : "=r"(r0), "=r"(r1) : "r"(addr));
}
__device__ __forceinline__ void mma_f16(float* c, unsigned a0, unsigned a1,
                                        unsigned a2, unsigned a3,
                                        unsigned b0, unsigned b1) {
    asm volatile(
        "mma.sync.aligned.m16n8k16.row.col.f32.f16.f16.f32 "
        "{%0,%1,%2,%3}, {%4,%5,%6,%7}, {%8,%9}, {%0,%1,%2,%3};"
        : "+f"(c[0]), "+f"(c[1]), "+f"(c[2]), "+f"(c[3])
        : "r"(a0), "r"(a1), "r"(a2), "r"(a3), "r"(b0), "r"(b1));
}

// ---------------------------------------------------------------------------
// Layer GEMM (fp16 HMMA): out[N,64] = (in[N,64] @ W[64,64]) * dinv[row] -> fp16
// 256 thr / 8 warps, 128-row tile. xs[128][64] fp16 + wt[64(n)][64(k)] fp16,
// both swizzled in 16B chunks: phys_chunk = chunk ^ (row & 7)  -> ldmatrix and
// staging are bank-conflict-free. IT = float (layer 1) or __half (layer 2).
// ---------------------------------------------------------------------------
template <typename IT>
__global__ void __launch_bounds__(256) gemm_hmma_k(
        const IT* __restrict__ in, const float* __restrict__ W,
        __half* __restrict__ out, int N) {
    __shared__ __align__(16) __half xs[128 * 64];
    __shared__ __align__(16) __half wt[64 * 64];

    const int t = threadIdx.x;
    const int row0 = blockIdx.x * 128;

    // stage W transposed: wt[n][k] = W[k][n], swizzled
    #pragma unroll
    for (int i = t; i < 4096; i += 256) {
        int k = i >> 6, n = i & 63;
        int off = n * 128 + ((((k >> 3) ^ (n & 7)) << 4) | ((k & 7) << 1));
        *reinterpret_cast<__half*>(reinterpret_cast<char*>(wt) + off) =
            __float2half_rn(W[i]);
    }

    // stage x tile as fp16 in 16B chunks
    #pragma unroll
    for (int i = t; i < 1024; i += 256) {
        int r = i >> 3, c = i & 7;
        int gr = row0 + r;
        uint4 val = make_uint4(0, 0, 0, 0);
        if (gr < N) {
            if constexpr (sizeof(IT) == 2) {
                val = reinterpret_cast<const uint4*>(in)[(size_t)gr * 8 + c];
            } else {
                const float4* fp = reinterpret_cast<const float4*>(in) +
                                   (size_t)gr * 16 + c * 2;
                float4 f0 = fp[0], f1 = fp[1];
                __half2 h0 = __floats2half2_rn(f0.x, f0.y);
                __half2 h1 = __floats2half2_rn(f0.z, f0.w);
                __half2 h2 = __floats2half2_rn(f1.x, f1.y);
                __half2 h3 = __floats2half2_rn(f1.z, f1.w);
                val.x = *reinterpret_cast<unsigned*>(&h0);
                val.y = *reinterpret_cast<unsigned*>(&h1);
                val.z = *reinterpret_cast<unsigned*>(&h2);
                val.w = *reinterpret_cast<unsigned*>(&h3);
            }
        }
        *reinterpret_cast<uint4*>(reinterpret_cast<char*>(xs) +
                                  r * 128 + ((c ^ (r & 7)) << 4)) = val;
    }
    __syncthreads();

    const int lane = t & 31;
    const int w = t >> 5;
    const int r0 = w * 16;

    unsigned xs_base = (unsigned)__cvta_generic_to_shared(xs);
    unsigned wt_base = (unsigned)__cvta_generic_to_shared(wt);

    float acc[8][4];
    #pragma unroll
    for (int ng = 0; ng < 8; ng++)
        #pragma unroll
        for (int j = 0; j < 4; j++) acc[ng][j] = 0.0f;

    const int arow  = r0 + (lane & 7) + ((lane >> 3) & 1) * 8;
    const int brl   = lane & 7;                    // B matrix row within 8

    #pragma unroll
    for (int k0 = 0; k0 < 64; k0 += 16) {
        int ac = (k0 >> 3) + (lane >> 4);
        unsigned aaddr = xs_base + arow * 128 + (((ac ^ (arow & 7)) & 7) << 4);
        unsigned a0, a1, a2, a3;
        ldsm_x4(a0, a1, a2, a3, aaddr);

        int bc = (k0 >> 3) + ((lane >> 3) & 1);
        unsigned bbase = wt_base + brl * 128 + (((bc ^ brl) & 7) << 4);
        #pragma unroll
        for (int ng = 0; ng < 8; ng++) {
            unsigned b0, b1;
            ldsm_x2(b0, b1, bbase + ng * 1024);    // +8 rows per n-group
            mma_f16(acc[ng], a0, a1, a2, a3, b0, b1);
        }
    }

    int gr1 = row0 + r0 + (lane >> 2);
    int gr2 = gr1 + 8;
    float sc1 = (gr1 < N) ? rsqrtf((float)g_cnt[gr1] + 1.0f) : 0.0f;
    float sc2 = (gr2 < N) ? rsqrtf((float)g_cnt[gr2] + 1.0f) : 0.0f;

    #pragma unroll
    for (int ng = 0; ng < 8; ng++) {
        int col = ng * 8 + (lane & 3) * 2;
        if (gr1 < N)
            *reinterpret_cast<__half2*>(out + (size_t)gr1 * 64 + col) =
                __floats2half2_rn(acc[ng][0] * sc1, acc[ng][1] * sc1);
        if (gr2 < N)
            *reinterpret_cast<__half2*>(out + (size_t)gr2 * 64 + col) =
                __floats2half2_rn(acc[ng][2] * sc2, acc[ng][3] * sc2);
    }
}

// ---------------------------------------------------------------------------
// Head GEMM (fp32 FFMA): out[N,32] = relu(in + preb) @ Wf + postb
// ---------------------------------------------------------------------------
__global__ void __launch_bounds__(256) gemm_head_k(
        const float* __restrict__ in, const float* __restrict__ W,
        const float* __restrict__ preb, const float* __restrict__ postb,
        float* __restrict__ out, int N) {
    constexpr int NOUT = 32, CPT = 2;
    __shared__ float xs[64][65];
    __shared__ __align__(16) float Ws[64 * NOUT];

    const int t = threadIdx.x;
    const int row0 = blockIdx.x * 64;

    #pragma unroll
    for (int i = t; i < 64 * NOUT; i += 256) Ws[i] = W[i];

    #pragma unroll
    for (int i = 0; i < 16; i++) {
        int lin = t + i * 256;
        int r = lin >> 6, c = lin & 63;
        int gr = row0 + r;
        float v = (gr < N) ? in[(size_t)gr * 64 + c] : 0.0f;
        v = fmaxf(v + preb[c], 0.0f);
        xs[r][c] = v;
    }
    __syncthreads();

    const int r0 = (t >> 4) * 4;
    const int c0 = (t & 15) * CPT;

    float acc[4][CPT];
    #pragma unroll
    for (int i = 0; i < 4; i++)
        #pragma unroll
        for (int j = 0; j < CPT; j++) acc[i][j] = 0.0f;

    #pragma unroll
    for (int k = 0; k < 64; k++) {
        float wv[CPT];
        #pragma unroll
        for (int j = 0; j < CPT; j++) wv[j] = Ws[k * NOUT + c0 + j];
        #pragma unroll
        for (int i = 0; i < 4; i++) {
            float a = xs[r0 + i][k];
            #pragma unroll
            for (int j = 0; j < CPT; j++)
                acc[i][j] = fmaf(a, wv[j], acc[i][j]);
        }
    }

    #pragma unroll
    for (int i = 0; i < 4; i++) {
        int gr = row0 + r0 + i;
        if (gr < N) {
            #pragma unroll
            for (int j = 0; j < CPT; j++)
                out[(size_t)gr * NOUT + c0 + j] = acc[i][j] + postb[c0 + j];
        }
    }
}

// ---------------------------------------------------------------------------
// Aggregation: warp per node, quarter-warp gathers, fp16 4-edge tree.
// ---------------------------------------------------------------------------
__device__ __forceinline__ uint4 hadd2_u4(uint4 a, uint4 b) {
    uint4 r;
    *reinterpret_cast<__half2*>(&r.x) = __hadd2(*reinterpret_cast<__half2*>(&a.x),
                                                *reinterpret_cast<__half2*>(&b.x));
    *reinterpret_cast<__half2*>(&r.y) = __hadd2(*reinterpret_cast<__half2*>(&a.y),
                                                *reinterpret_cast<__half2*>(&b.y));
    *reinterpret_cast<__half2*>(&r.z) = __hadd2(*reinterpret_cast<__half2*>(&a.z),
                                                *reinterpret_cast<__half2*>(&b.z));
    *reinterpret_cast<__half2*>(&r.w) = __hadd2(*reinterpret_cast<__half2*>(&a.w),
                                                *reinterpret_cast<__half2*>(&b.w));
    return r;
}

__device__ __forceinline__ void addf32_u4(float* acc, uint4 v) {
    float2 f;
    f = __half22float2(*reinterpret_cast<__half2*>(&v.x)); acc[0] += f.x; acc[1] += f.y;
    f = __half22float2(*reinterpret_cast<__half2*>(&v.y)); acc[2] += f.x; acc[3] += f.y;
    f = __half22float2(*reinterpret_cast<__half2*>(&v.z)); acc[4] += f.x; acc[5] += f.y;
    f = __half22float2(*reinterpret_cast<__half2*>(&v.w)); acc[6] += f.x; acc[7] += f.y;
}

template <bool ACT>
__global__ void __launch_bounds__(256) agg_k(
        float* __restrict__ outb, const float* __restrict__ bias, int N) {
    int warp = (blockIdx.x * blockDim.x + threadIdx.x) >> 5;
    int lane = threadIdx.x & 31;
    if (warp >= N) return;
    int q = lane & 7;
    int g = lane >> 3;

    const char* __restrict__ hbase = reinterpret_cast<const char*>(g_A) + q * 16;
    const int*  __restrict__ row   = g_csr + (size_t)warp * CAP;
    int cnt = g_cnt[warp];
    if (cnt > CAP) cnt = CAP;

    float acc[8] = {0, 0, 0, 0, 0, 0, 0, 0};

    if (g == 0) {   // self-loop row
        uint4 v = *reinterpret_cast<const uint4*>(hbase + (size_t)warp * 128);
        addf32_u4(acc, v);
    }

    for (int b = 0; b < cnt; b += 16) {
        int4 idx = *reinterpret_cast<const int4*>(row + b + 4 * g);
        uint4 v0 = *reinterpret_cast<const uint4*>(hbase + idx.x);
        uint4 v1 = *reinterpret_cast<const uint4*>(hbase + idx.y);
        uint4 v2 = *reinterpret_cast<const uint4*>(hbase + idx.z);
        uint4 v3 = *reinterpret_cast<const uint4*>(hbase + idx.w);
        uint4 t = hadd2_u4(hadd2_u4(v0, v1), hadd2_u4(v2, v3));
        addf32_u4(acc, t);
    }

    #pragma unroll
    for (int i = 0; i < 8; i++) {
        acc[i] += __shfl_xor_sync(0xffffffffu, acc[i], 8);
        acc[i] += __shfl_xor_sync(0xffffffffu, acc[i], 16);
    }

    float di = rsqrtf((float)g_cnt[warp] + 1.0f);
    if (g < 2) {
        int col = q * 8 + g * 4;
        if constexpr (ACT) {
            float v0 = fmaxf(acc[g * 4 + 0] * di + bias[col + 0], 0.0f);
            float v1 = fmaxf(acc[g * 4 + 1] * di + bias[col + 1], 0.0f);
            float v2 = fmaxf(acc[g * 4 + 2] * di + bias[col + 2], 0.0f);
            float v3 = fmaxf(acc[g * 4 + 3] * di + bias[col + 3], 0.0f);
            __half2* hout = reinterpret_cast<__half2*>(outb);
            hout[((size_t)warp * 64 + col) >> 1]       = __floats2half2_rn(v0, v1);
            hout[(((size_t)warp * 64 + col) >> 1) + 1] = __floats2half2_rn(v2, v3);
        } else {
            float4 w = make_float4(acc[g * 4 + 0] * di, acc[g * 4 + 1] * di,
                                   acc[g * 4 + 2] * di, acc[g * 4 + 3] * di);
            *reinterpret_cast<float4*>(outb + (size_t)warp * 64 + col) = w;
        }
    }
}

// ---------------------------------------------------------------------------
// launch
// ---------------------------------------------------------------------------
extern "C" void kernel_launch(void* const* d_in, const int* in_sizes, int n_in,
                              void* d_out, int out_size) {
    const float* x  = (const float*)d_in[0];
    const int*   ei = (const int*)d_in[1];
    const float* W1 = (const float*)d_in[2];
    const float* b1 = (const float*)d_in[3];
    const float* W2 = (const float*)d_in[4];
    const float* b2 = (const float*)d_in[5];
    const float* Wf = (const float*)d_in[6];
    const float* bf = (const float*)d_in[7];
    float* out = (float*)d_out;

    const int N = in_sizes[0] / 64;
    const int E = in_sizes[1] / 2;

    __half* pA = nullptr;
    float*  pB = nullptr;
    cudaGetSymbolAddress((void**)&pA, g_A);
    cudaGetSymbolAddress((void**)&pB, g_B);

    const int T = 256;
    dim3 bn((N + T - 1) / T), be((E + T - 1) / T);
    dim3 bg128((N + 127) / 128), bg64((N + 63) / 64);
    dim3 bagg((N * 32 + T - 1) / T);

    zero_k<<<bn, T>>>(N);
    fill_k<<<be, T>>>(ei, E, N);
    pad_k<<<bn, T>>>(N);

    // layer 1: h' = (x @ W1) * dinv (fp16 HMMA)
    gemm_hmma_k<float><<<bg128, T>>>(x, W1, pA, N);
    agg_k<true><<<bagg, T>>>(pB, b1, N);     // writes fp16 relu(agg+b1)

    // layer 2: h' = (act1 @ W2) * dinv (fp16 in, fp16 HMMA)
    gemm_hmma_k<__half><<<bg128, T>>>((const __half*)pB, W2, pA, N);
    agg_k<false><<<bagg, T>>>(pB, nullptr, N);  // fp32 out for head

    // head: out = relu(agg2 + b2) @ Wf + bf (fp32 FFMA)
    gemm_head_k<<<bg64, T>>>(pB, Wf, b2, bf, out, N);
}

// round 13
// speedup vs baseline: 1.2921x; 1.1957x over previous
#include <cuda_runtime.h>
#include <cuda_fp16.h>
#include <cstdint>

#define MAXN 100000
#define CAP 128            // per-node CSR bucket capacity, multiple of 4
#define ZOFF (MAXN << 7)   // byte offset of the permanently-zero h' row

// Scratch (__device__ globals; allocation-free rule)
__device__ __align__(16) __half g_A[(MAXN + 1) * 64];  // h' fp16; row MAXN stays 0
__device__ __align__(16) float  g_B[MAXN * 64];        // agg out (fp16-aliased)
__device__ int g_cnt[MAXN];
__device__ __align__(16) int g_csr[MAXN * CAP];        // src row BYTE offsets (s<<7)

// ---------------------------------------------------------------------------
// prep
// ---------------------------------------------------------------------------
__global__ void zero_k(int N) {
    int i = blockIdx.x * blockDim.x + threadIdx.x;
    if (i < N) g_cnt[i] = 0;
}

__global__ void fill_k(const int* __restrict__ ei, int E, int N) {
    int e = blockIdx.x * blockDim.x + threadIdx.x;
    if (e >= E) return;
    int s = __ldg(ei + e);
    int d = __ldg(ei + (size_t)E + e);
    if ((unsigned)s >= (unsigned)N) s = 0;
    if ((unsigned)d >= (unsigned)N) d = 0;
    int pos = atomicAdd(&g_cnt[d], 1);
    if (pos < CAP) g_csr[(size_t)d * CAP + pos] = s << 7;
}

__global__ void pad_k(int N) {
    int i = blockIdx.x * blockDim.x + threadIdx.x;
    if (i >= N) return;
    int c = g_cnt[i];
    if (c > CAP) c = CAP;
    int end = (c + 3) & ~3;
    int* row = g_csr + (size_t)i * CAP;
    for (int j = c; j < end; j++) row[j] = ZOFF;
}

// ---------------------------------------------------------------------------
// HMMA helpers
// ---------------------------------------------------------------------------
__device__ __forceinline__ void ldsm_x4(unsigned& r0, unsigned& r1,
                                        unsigned& r2, unsigned& r3, unsigned addr) {
    asm volatile("ldmatrix.sync.aligned.m8n8.x4.shared.b16 {%0,%1,%2,%3}, [%4];"
                 : "=r"(r0), "=r"(r1), "=r"(r2), "=r"(r3) : "r"(addr));
}
__device__ __forceinline__ void ldsm_x2(unsigned& r0, unsigned& r1, unsigned addr) {
    asm volatile("ldmatrix.sync.aligned.m8n8.x2.shared.b16 {%0,%1}, [%2];"
                 : "=r"(r0), "=r"(r1) : "r"(addr));
}
__device__ __forceinline__ void mma_f16(float* c, unsigned a0, unsigned a1,
                                        unsigned a2, unsigned a3,
                                        unsigned b0, unsigned b1) {
    asm volatile(
        "mma.sync.aligned.m16n8k16.row.col.f32.f16.f16.f32 "
        "{%0,%1,%2,%3}, {%4,%5,%6,%7}, {%8,%9}, {%0,%1,%2,%3};"
        : "+f"(c[0]), "+f"(c[1]), "+f"(c[2]), "+f"(c[3])
        : "r"(a0), "r"(a1), "r"(a2), "r"(a3), "r"(b0), "r"(b1));
}

// ---------------------------------------------------------------------------
// Layer GEMM (fp16 HMMA): out[N,64] = (in[N,64] @ W[64,64]) * dinv[row] -> fp16
// ---------------------------------------------------------------------------
template <typename IT>
__global__ void __launch_bounds__(256) gemm_hmma_k(
        const IT* __restrict__ in, const float* __restrict__ W,
        __half* __restrict__ out, int N) {
    __shared__ __align__(16) __half xs[128 * 64];
    __shared__ __align__(16) __half wt[64 * 64];

    const int t = threadIdx.x;
    const int row0 = blockIdx.x * 128;

    // stage W transposed: wt[n][k] = W[k][n], swizzled
    #pragma unroll
    for (int i = t; i < 4096; i += 256) {
        int k = i >> 6, n = i & 63;
        int off = n * 128 + ((((k >> 3) ^ (n & 7)) << 4) | ((k & 7) << 1));
        *reinterpret_cast<__half*>(reinterpret_cast<char*>(wt) + off) =
            __float2half_rn(W[i]);
    }

    // stage x tile as fp16 in 16B chunks
    #pragma unroll
    for (int i = t; i < 1024; i += 256) {
        int r = i >> 3, c = i & 7;
        int gr = row0 + r;
        uint4 val = make_uint4(0, 0, 0, 0);
        if (gr < N) {
            if constexpr (sizeof(IT) == 2) {
                val = reinterpret_cast<const uint4*>(in)[(size_t)gr * 8 + c];
            } else {
                const float4* fp = reinterpret_cast<const float4*>(in) +
                                   (size_t)gr * 16 + c * 2;
                float4 f0 = fp[0], f1 = fp[1];
                __half2 h0 = __floats2half2_rn(f0.x, f0.y);
                __half2 h1 = __floats2half2_rn(f0.z, f0.w);
                __half2 h2 = __floats2half2_rn(f1.x, f1.y);
                __half2 h3 = __floats2half2_rn(f1.z, f1.w);
                val.x = *reinterpret_cast<unsigned*>(&h0);
                val.y = *reinterpret_cast<unsigned*>(&h1);
                val.z = *reinterpret_cast<unsigned*>(&h2);
                val.w = *reinterpret_cast<unsigned*>(&h3);
            }
        }
        *reinterpret_cast<uint4*>(reinterpret_cast<char*>(xs) +
                                  r * 128 + ((c ^ (r & 7)) << 4)) = val;
    }
    __syncthreads();

    const int lane = t & 31;
    const int w = t >> 5;
    const int r0 = w * 16;

    unsigned xs_base = (unsigned)__cvta_generic_to_shared(xs);
    unsigned wt_base = (unsigned)__cvta_generic_to_shared(wt);

    float acc[8][4];
    #pragma unroll
    for (int ng = 0; ng < 8; ng++)
        #pragma unroll
        for (int j = 0; j < 4; j++) acc[ng][j] = 0.0f;

    const int arow = r0 + (lane & 7) + ((lane >> 3) & 1) * 8;
    const int brl  = lane & 7;

    #pragma unroll
    for (int k0 = 0; k0 < 64; k0 += 16) {
        int ac = (k0 >> 3) + (lane >> 4);
        unsigned aaddr = xs_base + arow * 128 + (((ac ^ (arow & 7)) & 7) << 4);
        unsigned a0, a1, a2, a3;
        ldsm_x4(a0, a1, a2, a3, aaddr);

        int bc = (k0 >> 3) + ((lane >> 3) & 1);
        unsigned bbase = wt_base + brl * 128 + (((bc ^ brl) & 7) << 4);
        #pragma unroll
        for (int ng = 0; ng < 8; ng++) {
            unsigned b0, b1;
            ldsm_x2(b0, b1, bbase + ng * 1024);
            mma_f16(acc[ng], a0, a1, a2, a3, b0, b1);
        }
    }

    int gr1 = row0 + r0 + (lane >> 2);
    int gr2 = gr1 + 8;
    float sc1 = (gr1 < N) ? rsqrtf((float)g_cnt[gr1] + 1.0f) : 0.0f;
    float sc2 = (gr2 < N) ? rsqrtf((float)g_cnt[gr2] + 1.0f) : 0.0f;

    #pragma unroll
    for (int ng = 0; ng < 8; ng++) {
        int col = ng * 8 + (lane & 3) * 2;
        if (gr1 < N)
            *reinterpret_cast<__half2*>(out + (size_t)gr1 * 64 + col) =
                __floats2half2_rn(acc[ng][0] * sc1, acc[ng][1] * sc1);
        if (gr2 < N)
            *reinterpret_cast<__half2*>(out + (size_t)gr2 * 64 + col) =
                __floats2half2_rn(acc[ng][2] * sc2, acc[ng][3] * sc2);
    }
}

// ---------------------------------------------------------------------------
// Head GEMM (fp32 FFMA, fp16 input already activated): out = in @ Wf + bf
// ---------------------------------------------------------------------------
__global__ void __launch_bounds__(256) gemm_head_k(
        const __half* __restrict__ in, const float* __restrict__ W,
        const float* __restrict__ postb, float* __restrict__ out, int N) {
    constexpr int NOUT = 32, CPT = 2;
    __shared__ float xs[64][65];
    __shared__ __align__(16) float Ws[64 * NOUT];

    const int t = threadIdx.x;
    const int row0 = blockIdx.x * 64;

    #pragma unroll
    for (int i = t; i < 64 * NOUT; i += 256) Ws[i] = W[i];

    // vectorized fp16 staging: 512 chunks of 8 halves
    #pragma unroll
    for (int i = t; i < 512; i += 256) {
        int r = i >> 3, c8 = (i & 7) * 8;
        int gr = row0 + r;
        uint4 val = make_uint4(0, 0, 0, 0);
        if (gr < N) val = reinterpret_cast<const uint4*>(in)[(size_t)gr * 8 + (i & 7)];
        const __half2* h = reinterpret_cast<const __half2*>(&val);
        #pragma unroll
        for (int j = 0; j < 4; j++) {
            float2 f = __half22float2(h[j]);
            xs[r][c8 + 2 * j]     = f.x;
            xs[r][c8 + 2 * j + 1] = f.y;
        }
    }
    __syncthreads();

    const int r0 = (t >> 4) * 4;
    const int c0 = (t & 15) * CPT;

    float acc[4][CPT];
    #pragma unroll
    for (int i = 0; i < 4; i++)
        #pragma unroll
        for (int j = 0; j < CPT; j++) acc[i][j] = 0.0f;

    #pragma unroll
    for (int k = 0; k < 64; k++) {
        float wv[CPT];
        #pragma unroll
        for (int j = 0; j < CPT; j++) wv[j] = Ws[k * NOUT + c0 + j];
        #pragma unroll
        for (int i = 0; i < 4; i++) {
            float a = xs[r0 + i][k];
            #pragma unroll
            for (int j = 0; j < CPT; j++)
                acc[i][j] = fmaf(a, wv[j], acc[i][j]);
        }
    }

    #pragma unroll
    for (int i = 0; i < 4; i++) {
        int gr = row0 + r0 + i;
        if (gr < N) {
            #pragma unroll
            for (int j = 0; j < CPT; j++)
                out[(size_t)gr * NOUT + c0 + j] = acc[i][j] + postb[c0 + j];
        }
    }
}

// ---------------------------------------------------------------------------
// Aggregation: 8-lane group per node (4 nodes/warp). Lane q owns 16B = cols
// [8q,8q+8). Pad-to-4 CSR chunks; no cross-group fold. Writes fp16
// relu(agg*dinv + bias).
// ---------------------------------------------------------------------------
__device__ __forceinline__ uint4 hadd2_u4(uint4 a, uint4 b) {
    uint4 r;
    *reinterpret_cast<__half2*>(&r.x) = __hadd2(*reinterpret_cast<__half2*>(&a.x),
                                                *reinterpret_cast<__half2*>(&b.x));
    *reinterpret_cast<__half2*>(&r.y) = __hadd2(*reinterpret_cast<__half2*>(&a.y),
                                                *reinterpret_cast<__half2*>(&b.y));
    *reinterpret_cast<__half2*>(&r.z) = __hadd2(*reinterpret_cast<__half2*>(&a.z),
                                                *reinterpret_cast<__half2*>(&b.z));
    *reinterpret_cast<__half2*>(&r.w) = __hadd2(*reinterpret_cast<__half2*>(&a.w),
                                                *reinterpret_cast<__half2*>(&b.w));
    return r;
}

__device__ __forceinline__ void addf32_u4(float* acc, uint4 v) {
    float2 f;
    f = __half22float2(*reinterpret_cast<__half2*>(&v.x)); acc[0] += f.x; acc[1] += f.y;
    f = __half22float2(*reinterpret_cast<__half2*>(&v.y)); acc[2] += f.x; acc[3] += f.y;
    f = __half22float2(*reinterpret_cast<__half2*>(&v.z)); acc[4] += f.x; acc[5] += f.y;
    f = __half22float2(*reinterpret_cast<__half2*>(&v.w)); acc[6] += f.x; acc[7] += f.y;
}

__global__ void __launch_bounds__(256) agg_k(
        float* __restrict__ outb, const float* __restrict__ bias, int N) {
    int gidx = blockIdx.x * blockDim.x + threadIdx.x;
    int n = gidx >> 3;
    int q = gidx & 7;
    if (n >= N) return;

    const char* __restrict__ hbase = reinterpret_cast<const char*>(g_A) + q * 16;
    const int*  __restrict__ row   = g_csr + (size_t)n * CAP;
    int rcnt = g_cnt[n];
    int cnt = rcnt > CAP ? CAP : rcnt;
    int pcnt = (cnt + 3) & ~3;

    float acc[8];
    {   // self-loop row
        uint4 v = *reinterpret_cast<const uint4*>(hbase + (size_t)n * 128);
        float2 f;
        f = __half22float2(*reinterpret_cast<__half2*>(&v.x)); acc[0] = f.x; acc[1] = f.y;
        f = __half22float2(*reinterpret_cast<__half2*>(&v.y)); acc[2] = f.x; acc[3] = f.y;
        f = __half22float2(*reinterpret_cast<__half2*>(&v.z)); acc[4] = f.x; acc[5] = f.y;
        f = __half22float2(*reinterpret_cast<__half2*>(&v.w)); acc[6] = f.x; acc[7] = f.y;
    }

    int b = 0;
    for (; b + 8 <= pcnt; b += 8) {      // 8 gathers in flight
        int4 i0 = *reinterpret_cast<const int4*>(row + b);
        int4 i1 = *reinterpret_cast<const int4*>(row + b + 4);
        uint4 v0 = *reinterpret_cast<const uint4*>(hbase + i0.x);
        uint4 v1 = *reinterpret_cast<const uint4*>(hbase + i0.y);
        uint4 v2 = *reinterpret_cast<const uint4*>(hbase + i0.z);
        uint4 v3 = *reinterpret_cast<const uint4*>(hbase + i0.w);
        uint4 v4 = *reinterpret_cast<const uint4*>(hbase + i1.x);
        uint4 v5 = *reinterpret_cast<const uint4*>(hbase + i1.y);
        uint4 v6 = *reinterpret_cast<const uint4*>(hbase + i1.z);
        uint4 v7 = *reinterpret_cast<const uint4*>(hbase + i1.w);
        addf32_u4(acc, hadd2_u4(hadd2_u4(v0, v1), hadd2_u4(v2, v3)));
        addf32_u4(acc, hadd2_u4(hadd2_u4(v4, v5), hadd2_u4(v6, v7)));
    }
    if (b < pcnt) {
        int4 i0 = *reinterpret_cast<const int4*>(row + b);
        uint4 v0 = *reinterpret_cast<const uint4*>(hbase + i0.x);
        uint4 v1 = *reinterpret_cast<const uint4*>(hbase + i0.y);
        uint4 v2 = *reinterpret_cast<const uint4*>(hbase + i0.z);
        uint4 v3 = *reinterpret_cast<const uint4*>(hbase + i0.w);
        addf32_u4(acc, hadd2_u4(hadd2_u4(v0, v1), hadd2_u4(v2, v3)));
    }

    float di = rsqrtf((float)rcnt + 1.0f);
    float4 bi0 = *reinterpret_cast<const float4*>(bias + q * 8);
    float4 bi1 = *reinterpret_cast<const float4*>(bias + q * 8 + 4);
    float r0 = fmaxf(fmaf(acc[0], di, bi0.x), 0.0f);
    float r1 = fmaxf(fmaf(acc[1], di, bi0.y), 0.0f);
    float r2 = fmaxf(fmaf(acc[2], di, bi0.z), 0.0f);
    float r3 = fmaxf(fmaf(acc[3], di, bi0.w), 0.0f);
    float r4 = fmaxf(fmaf(acc[4], di, bi1.x), 0.0f);
    float r5 = fmaxf(fmaf(acc[5], di, bi1.y), 0.0f);
    float r6 = fmaxf(fmaf(acc[6], di, bi1.z), 0.0f);
    float r7 = fmaxf(fmaf(acc[7], di, bi1.w), 0.0f);

    __half2 h0 = __floats2half2_rn(r0, r1);
    __half2 h1 = __floats2half2_rn(r2, r3);
    __half2 h2 = __floats2half2_rn(r4, r5);
    __half2 h3 = __floats2half2_rn(r6, r7);
    uint4 pack;
    pack.x = *reinterpret_cast<unsigned*>(&h0);
    pack.y = *reinterpret_cast<unsigned*>(&h1);
    pack.z = *reinterpret_cast<unsigned*>(&h2);
    pack.w = *reinterpret_cast<unsigned*>(&h3);
    *reinterpret_cast<uint4*>(reinterpret_cast<char*>(outb) + (size_t)n * 128 + q * 16) = pack;
}

// ---------------------------------------------------------------------------
// launch
// ---------------------------------------------------------------------------
extern "C" void kernel_launch(void* const* d_in, const int* in_sizes, int n_in,
                              void* d_out, int out_size) {
    const float* x  = (const float*)d_in[0];
    const int*   ei = (const int*)d_in[1];
    const float* W1 = (const float*)d_in[2];
    const float* b1 = (const float*)d_in[3];
    const float* W2 = (const float*)d_in[4];
    const float* b2 = (const float*)d_in[5];
    const float* Wf = (const float*)d_in[6];
    const float* bf = (const float*)d_in[7];
    float* out = (float*)d_out;

    const int N = in_sizes[0] / 64;
    const int E = in_sizes[1] / 2;

    __half* pA = nullptr;
    float*  pB = nullptr;
    cudaGetSymbolAddress((void**)&pA, g_A);
    cudaGetSymbolAddress((void**)&pB, g_B);

    const int T = 256;
    dim3 bn((N + T - 1) / T), be((E + T - 1) / T);
    dim3 bg128((N + 127) / 128), bg64((N + 63) / 64);
    dim3 bagg((N * 8 + T - 1) / T);

    zero_k<<<bn, T>>>(N);
    fill_k<<<be, T>>>(ei, E, N);
    pad_k<<<bn, T>>>(N);

    // layer 1: h' = (x @ W1) * dinv (fp16 HMMA)
    gemm_hmma_k<float><<<bg128, T>>>(x, W1, pA, N);
    agg_k<<<bagg, T>>>(pB, b1, N);   // fp16 relu(agg+b1)

    // layer 2: h' = (act1 @ W2) * dinv (fp16 HMMA)
    gemm_hmma_k<__half><<<bg128, T>>>((const __half*)pB, W2, pA, N);
    agg_k<<<bagg, T>>>(pB, b2, N);   // fp16 relu(agg+b2)

    // head: out = act2 @ Wf + bf (fp32 FFMA, fp16 input)
    gemm_head_k<<<bg64, T>>>((const __half*)pB, Wf, bf, out, N);
}